// round 17
// baseline (speedup 1.0000x reference)
#include <cuda_runtime.h>
#include <cuda_fp16.h>
#include <cstdint>
#include <cstddef>

#define NE 800000
#define NN 50000
#define IN_CH 128
#define HID 64
#define OUT_CH 128
#define NT 6250          // 128-edge tiles (stage1)
#define NT2 12500        // 64-edge tiles (stage2)
#define RS2 0.70710678118654752f

// ---- stage1 smem (bytes), pitch 272B: A 34816, W_in 17408, W_skip 34816 ----
#define S1_A 0
#define S1_W 34816
#define S1_W2 52224
#define SMEM1 87296

// ---- stage2 smem (bytes), pitch 144B: 2 Y buffers (64x144), W_out 128x144 ----
#define A2_GRP 9216
#define W2_F   18432
#define S2_BV  36864
#define SMEM2  37888

// Node hidden state (complex interleaved [NN][64] floats), 12.8 MB scratch.
__device__ float g_h[(size_t)NN * HID];
// Pre-computed skip = EA @ W_skip^T in fp16, written by stage1. 204.8 MB.
__device__ uint2 g_sk[(size_t)NE * 32];   // [e][128 fp16] = 256B/edge

// ---------------------------------------------------------------------------
// Helpers
// ---------------------------------------------------------------------------
__device__ __forceinline__ uint32_t smem_u32(const void* p) {
    uint32_t a;
    asm("{ .reg .u64 t; cvta.to.shared.u64 t, %1; cvt.u32.u64 %0, t; }"
        : "=r"(a) : "l"(p));
    return a;
}

// Within-16 output-channel permutation: fragment pair (nf, nf+1) holds 4
// consecutive actual columns. smem row s holds actual col a:
// s = nf*8 + 2t + j  <->  a = 4t + 2nf + j.
__device__ __forceinline__ int perm16(int a) {
    return ((a >> 1) & 1) * 8 + (a >> 2) * 2 + (a & 1);
}
__device__ __forceinline__ int permrow(int n) {
    return (n & ~15) | perm16(n & 15);
}

__device__ __forceinline__ int detect_kind(const void* mraw, int* sflags) {
    if (threadIdx.x < 2) sflags[threadIdx.x] = 0;
    __syncthreads();
    int l1 = 0, l23 = 0;
    const unsigned char* m = (const unsigned char*)mraw;
    for (int i = threadIdx.x; i < 2048; i += blockDim.x) {
        unsigned char b = m[i];
        if (b) {
            int r = i & 3;
            if (r == 1) l1 = 1;
            else if (r >= 2) l23 = 1;
        }
    }
    if (l1) atomicOr(&sflags[0], 1);
    if (l23) atomicOr(&sflags[1], 1);
    __syncthreads();
    return sflags[0] ? 0 : (sflags[1] ? 2 : 1);
}
__device__ __forceinline__ bool read_mask(const void* m, int kind, int e) {
    if (kind == 0) return ((const unsigned char*)m)[e] != 0;
    if (kind == 1) return ((const int*)m)[e] != 0;
    return ((const float*)m)[e] != 0.0f;
}

// pack two floats into fp16x2 (lower = f0, upper = f1)
__device__ __forceinline__ uint32_t f16x2(float f0, float f1) {
    uint32_t r;
    asm("cvt.rn.f16x2.f32 %0, %1, %2;" : "=r"(r) : "f"(f1), "f"(f0));
    return r;
}

__device__ __forceinline__ void mmaf16(float* c, const uint32_t* a,
                                       const uint32_t* b) {
    asm volatile(
        "mma.sync.aligned.m16n8k16.row.col.f32.f16.f16.f32 "
        "{%0,%1,%2,%3}, {%4,%5,%6,%7}, {%8,%9}, {%0,%1,%2,%3};"
        : "+f"(c[0]), "+f"(c[1]), "+f"(c[2]), "+f"(c[3])
        : "r"(a[0]), "r"(a[1]), "r"(a[2]), "r"(a[3]), "r"(b[0]), "r"(b[1]));
}

#define LDSM4(r, addr)                                                         \
    asm volatile("ldmatrix.sync.aligned.m8n8.x4.shared.b16 {%0,%1,%2,%3}, [%4];"\
        : "=r"((r)[0]), "=r"((r)[1]), "=r"((r)[2]), "=r"((r)[3]) : "r"(addr))

__device__ __forceinline__ void red_v4(float* p, float a, float b, float c,
                                       float d) {
    asm volatile("red.global.add.v4.f32 [%0], {%1,%2,%3,%4};"
                 :: "l"(p), "f"(a), "f"(b), "f"(c), "f"(d) : "memory");
}

__device__ __forceinline__ void bar_grp(int id) {
    asm volatile("bar.sync %0, 256;" :: "r"(id) : "memory");
}

// lane-split metadata: lanes 0-7 load u(row), 8-15 v(row), 16-23 mask(row)
__device__ __forceinline__ int load_lane_meta(const int* __restrict__ ei,
                                              const void* __restrict__ m,
                                              int kind, int eb, int l) {
    if (l < 8) return ei[eb + l];
    if (l < 16) return ei[NE + eb + (l - 8)];
    if (l < 24) {
        int e = eb + (l - 16);
        if (kind == 0) return ((const unsigned char*)m)[e];
        if (kind == 1) return ((const int*)m)[e];
        return (((const float*)m)[e] != 0.0f) ? 1 : 0;
    }
    return 0;
}

// ---------------------------------------------------------------------------
// Stage 1 (fp16): on each 128-edge tile, one shared A build then TWO GEMMs:
//   z    = EA @ W_in^T   (K=128, N=64)  -> rotate in regs, red.v4 into g_h
//   skip = EA @ W_skip^T (K=128, N=128) -> store fp16 to g_sk for stage2
// ---------------------------------------------------------------------------
__global__ void __launch_bounds__(512, 2) stage1_kernel(
    const float* __restrict__ ea, const float* __restrict__ Win,
    const float* __restrict__ Wskip, const int* __restrict__ ei,
    const void* __restrict__ mraw)
{
    extern __shared__ __align__(16) char sm1[];
    __shared__ int sflags[2];
    const int tid = threadIdx.x, w = tid >> 5, l = tid & 31;
    const int kind = detect_kind(mraw, sflags);
    const uint32_t sb = smem_u32(sm1);

    for (int x = tid; x < 64 * 64; x += 512) {       // W_in [64][128]
        int n = x >> 6, kp = x & 63;
        float2 wv = *(const float2*)(Win + n * IN_CH + 2 * kp);
        *(uint32_t*)(sm1 + S1_W + (uint32_t)(permrow(n) * 272 + 4 * kp)) =
            f16x2(wv.x, wv.y);
    }
    for (int x = tid; x < 128 * 64; x += 512) {      // W_skip [128][128]
        int n = x >> 6, kp = x & 63;
        float2 wv = *(const float2*)(Wskip + n * IN_CH + 2 * kp);
        *(uint32_t*)(sm1 + S1_W2 + (uint32_t)(permrow(n) * 272 + 4 * kp)) =
            f16x2(wv.x, wv.y);
    }

    const int wr = w >> 2, wc = w & 3;
    const int rowb = wr * 32, colb = wc * 16, colb2 = wc * 32;
    const int g = l >> 2, tig = l & 3;
    const uint32_t a_sub = (uint32_t)((rowb + ((l >> 3) & 1) * 8 + (l & 7)) * 272
                                      + (l >> 4) * 16);
    const uint32_t b_sub = (uint32_t)((colb + ((l >> 4) & 1) * 8 + (l & 7)) * 272
                                      + ((l >> 3) & 1) * 16);
    const uint32_t b2_sub = (uint32_t)((colb2 + ((l >> 4) & 1) * 8 + (l & 7)) * 272
                                       + ((l >> 3) & 1) * 16);

    for (int t = blockIdx.x; t < NT; t += gridDim.x) {
        // ---- build A rows w*8..w*8+7 (fp16) ----
        #pragma unroll 2
        for (int rr = 0; rr < 8; rr++) {
            int r = w * 8 + rr, e = t * 128 + r;
            float4 a4 = *(const float4*)(ea + (size_t)e * IN_CH + 4 * l);
            uint2 hv2;
            hv2.x = f16x2(a4.x, a4.y);
            hv2.y = f16x2(a4.z, a4.w);
            *(uint2*)(sm1 + S1_A + (uint32_t)(r * 272 + 8 * l)) = hv2;
        }
        int pu = ei[t * 128 + rowb + l];
        int pv = ei[NE + t * 128 + rowb + l];
        int pm = read_mask(mraw, kind, t * 128 + rowb + l) ? 1 : 0;
        __syncthreads();

        // ---- GEMM 1: z (N=64) ----
        float acc[2][2][4];
        #pragma unroll
        for (int mf = 0; mf < 2; mf++)
            #pragma unroll
            for (int nf = 0; nf < 2; nf++)
                #pragma unroll
                for (int i = 0; i < 4; i++) acc[mf][nf][i] = 0.f;
        {
            uint32_t aa0 = sb + S1_A + a_sub, aa1 = aa0 + 16 * 272;
            uint32_t ba = sb + S1_W + b_sub;
            #pragma unroll
            for (int ks = 0; ks < 8; ks++) {
                uint32_t A0[4], A1[4], B0[4];
                LDSM4(A0, aa0);
                LDSM4(A1, aa1);
                LDSM4(B0, ba);
                mmaf16(acc[0][0], A0, B0);
                mmaf16(acc[0][1], A0, B0 + 2);
                mmaf16(acc[1][0], A1, B0);
                mmaf16(acc[1][1], A1, B0 + 2);
                aa0 += 32; aa1 += 32; ba += 32;
            }
        }
        // register scatter (perm makes cols colb+4*tig..+3 consecutive)
        #pragma unroll
        for (int mf = 0; mf < 2; mf++) {
            #pragma unroll
            for (int rsel = 0; rsel < 2; rsel++) {
                int rloc = mf * 16 + g + rsel * 8;
                int u = __shfl_sync(0xffffffffu, pu, rloc);
                int v = __shfl_sync(0xffffffffu, pv, rloc);
                int mm = __shfl_sync(0xffffffffu, pm, rloc);
                float cc, ss, dinv;
                if (mm) { cc = 1.0f; ss = 0.0f; dinv = (u == v) ? 0.0f : RS2; }
                else    { cc = RS2;  ss = RS2;  dinv = RS2; }
                if (dinv != 0.0f) {
                    float r0 = acc[mf][0][2 * rsel] * dinv;
                    float i0 = acc[mf][0][2 * rsel + 1] * dinv;
                    float r1 = acc[mf][1][2 * rsel] * dinv;
                    float i1 = acc[mf][1][2 * rsel + 1] * dinv;
                    int cbase = colb + 4 * tig;
                    red_v4(g_h + (size_t)v * HID + cbase,
                           fmaf(cc, r0, ss * i0), fmaf(cc, i0, -ss * r0),
                           fmaf(cc, r1, ss * i1), fmaf(cc, i1, -ss * r1));
                    red_v4(g_h + (size_t)u * HID + cbase,
                           fmaf(-cc, r0, ss * i0), fmaf(-cc, i0, -ss * r0),
                           fmaf(-cc, r1, ss * i1), fmaf(-cc, i1, -ss * r1));
                }
            }
        }

        // ---- GEMM 2: skip (N=128), store fp16 to g_sk ----
        float acc2[2][4][4];
        #pragma unroll
        for (int mf = 0; mf < 2; mf++)
            #pragma unroll
            for (int nf = 0; nf < 4; nf++)
                #pragma unroll
                for (int i = 0; i < 4; i++) acc2[mf][nf][i] = 0.f;
        {
            uint32_t aa0 = sb + S1_A + a_sub, aa1 = aa0 + 16 * 272;
            uint32_t bb0 = sb + S1_W2 + b2_sub, bb1 = bb0 + 16 * 272;
            #pragma unroll
            for (int ks = 0; ks < 8; ks++) {
                uint32_t A0[4], A1[4], B0[4], B1[4];
                LDSM4(A0, aa0);
                LDSM4(A1, aa1);
                LDSM4(B0, bb0);
                LDSM4(B1, bb1);
                mmaf16(acc2[0][0], A0, B0);
                mmaf16(acc2[0][1], A0, B0 + 2);
                mmaf16(acc2[0][2], A0, B1);
                mmaf16(acc2[0][3], A0, B1 + 2);
                mmaf16(acc2[1][0], A1, B0);
                mmaf16(acc2[1][1], A1, B0 + 2);
                mmaf16(acc2[1][2], A1, B1);
                mmaf16(acc2[1][3], A1, B1 + 2);
                aa0 += 32; aa1 += 32; bb0 += 32; bb1 += 32;
            }
        }
        char* skb = (char*)g_sk;
        #pragma unroll
        for (int mf = 0; mf < 2; mf++) {
            int e0 = t * 128 + rowb + mf * 16 + g;
            #pragma unroll
            for (int hb = 0; hb < 2; hb++) {
                int n0 = 2 * hb, n1 = 2 * hb + 1;
                int c = colb2 + hb * 16 + 4 * tig;
                uint2 s0, s1;
                s0.x = f16x2(acc2[mf][n0][0], acc2[mf][n0][1]);
                s0.y = f16x2(acc2[mf][n1][0], acc2[mf][n1][1]);
                s1.x = f16x2(acc2[mf][n0][2], acc2[mf][n0][3]);
                s1.y = f16x2(acc2[mf][n1][2], acc2[mf][n1][3]);
                *(uint2*)(skb + (size_t)e0 * 256 + c * 2) = s0;
                *(uint2*)(skb + (size_t)(e0 + 8) * 256 + c * 2) = s1;
            }
        }
        __syncthreads();   // all warps done reading A before next build
    }
}

// ---------------------------------------------------------------------------
// Stage 2 (fp16, K=64 only): two-group ping-pong + tensor-phase mutex,
// A = Y (64x64), B = W_out (128x64, col-permuted). Epilogue adds fp16 skip
// from g_sk + bias, STG.128 stores.
// ---------------------------------------------------------------------------
__global__ void __launch_bounds__(512, 2) stage2_kernel(
    const float* __restrict__ Wout, const float* __restrict__ bskip,
    const float* __restrict__ bias, const int* __restrict__ ei,
    const void* __restrict__ mraw, float* __restrict__ out)
{
    extern __shared__ __align__(16) char sm[];
    __shared__ int sflags[2];
    __shared__ int s_sync[3];   // [0]=turn, [1]=done grp0, [2]=done grp1
    const int tid = threadIdx.x, l = tid & 31;
    const int kind = detect_kind(mraw, sflags);
    const uint32_t sb = smem_u32(sm);
    float* bv = (float*)(sm + S2_BV);

    if (tid < 3) s_sync[tid] = 0;

    for (int x = tid; x < 128 * 32; x += 512) {      // W_out [128][64]
        int n = x >> 5, kp = x & 31;
        float2 wv = *(const float2*)(Wout + n * HID + 2 * kp);
        *(uint32_t*)(sm + W2_F + (uint32_t)(permrow(n) * 144 + 4 * kp)) =
            f16x2(wv.x, wv.y);
    }
    if (tid < 128) bv[tid] = bskip[tid] + bias[tid];
    __syncthreads();

    const int grp = tid >> 8;            // 0 or 1
    const int gtid = tid & 255;
    const int w8 = (tid >> 5) & 7;
    const int barid = grp + 1;
    const uint32_t aBase = sb + (uint32_t)grp * A2_GRP;

    const int wr = w8 >> 2, wc = w8 & 3; // 2x4 warp grid over 64x128 output
    const int rowb = wr * 32, colb = wc * 32;
    const int g = l >> 2, tig = l & 3;
    const uint32_t a_sub = (uint32_t)((rowb + ((l >> 3) & 1) * 8 + (l & 7)) * 144
                                      + (l >> 4) * 16);
    const uint32_t b_sub = (uint32_t)((colb + ((l >> 4) & 1) * 8 + (l & 7)) * 144
                                      + ((l >> 3) & 1) * 16);

    const int t0 = blockIdx.x * 2 + grp;
    const int tstride = gridDim.x * 2;
    int pre = 0;
    if (t0 < NT2)
        pre = load_lane_meta(ei, mraw, kind, t0 * 64 + w8 * 8, l);

    for (int t = t0; t < NT2; t += tstride) {
        // ---- Phase A: gathers + Y build ----
        float2 phv[8], phu[8];
        #pragma unroll
        for (int r = 0; r < 8; r++) {
            int u = __shfl_sync(0xffffffffu, pre, r);
            int v = __shfl_sync(0xffffffffu, pre, r + 8);
            phv[r] = *(const float2*)(g_h + (size_t)v * HID + 2 * l);
            phu[r] = *(const float2*)(g_h + (size_t)u * HID + 2 * l);
        }
        #pragma unroll
        for (int rq = 0; rq < 8; rq++) {
            int r = w8 * 8 + rq;
            int u = __shfl_sync(0xffffffffu, pre, rq);
            int v = __shfl_sync(0xffffffffu, pre, rq + 8);
            int mm = __shfl_sync(0xffffffffu, pre, rq + 16);
            float cc, ss, dinv;
            if (mm) { cc = 1.0f; ss = 0.0f; dinv = (u == v) ? 0.0f : RS2; }
            else    { cc = RS2;  ss = RS2;  dinv = RS2; }
            float av = fmaxf(phv[rq].x, 0.f), bvv = fmaxf(phv[rq].y, 0.f);
            float au = fmaxf(phu[rq].x, 0.f), bu  = fmaxf(phu[rq].y, 0.f);
            float yr = dinv * (cc * (av - au) - ss * (bvv + bu));
            float yi = dinv * (cc * (bvv - bu) + ss * (av + au));
            *(uint32_t*)(sm + (aBase - sb)
                         + (uint32_t)(r * 144 + 4 * l)) = f16x2(yr, yi);
        }
        const int tn = t + tstride;
        int pre_n = (tn < NT2) ? load_lane_meta(ei, mraw, kind,
                                                tn * 64 + w8 * 8, l) : 0;
        bar_grp(barid);

        // ---- acquire tensor-phase ticket (perf-only mutex) ----
        if (gtid == 0) {
            volatile int* vs = s_sync;
            while (vs[0] != grp && vs[1 + (1 - grp)] == 0) { }
        }
        bar_grp(barid);

        // ---- Phase B: fp16 mma over K=64 ----
        float acc[2][4][4];
        #pragma unroll
        for (int mf = 0; mf < 2; mf++)
            #pragma unroll
            for (int nf = 0; nf < 4; nf++)
                #pragma unroll
                for (int i = 0; i < 4; i++) acc[mf][nf][i] = 0.f;
        {
            uint32_t aa0 = aBase + a_sub, aa1 = aa0 + 16 * 144;
            uint32_t bb0 = sb + W2_F + b_sub, bb1 = bb0 + 16 * 144;
            #pragma unroll
            for (int ks = 0; ks < 4; ks++) {
                uint32_t A0[4], A1[4], B0[4], B1[4];
                LDSM4(A0, aa0);
                LDSM4(A1, aa1);
                LDSM4(B0, bb0);
                LDSM4(B1, bb1);
                mmaf16(acc[0][0], A0, B0);
                mmaf16(acc[0][1], A0, B0 + 2);
                mmaf16(acc[0][2], A0, B1);
                mmaf16(acc[0][3], A0, B1 + 2);
                mmaf16(acc[1][0], A1, B0);
                mmaf16(acc[1][1], A1, B0 + 2);
                mmaf16(acc[1][2], A1, B1);
                mmaf16(acc[1][3], A1, B1 + 2);
                aa0 += 32; aa1 += 32; bb0 += 32; bb1 += 32;
            }
        }

        // ---- release ticket ----
        if (gtid == 0) ((volatile int*)s_sync)[0] = 1 - grp;

        // ---- Phase C: skip(fp16) + bias + STG.128 ----
        const char* skb = (const char*)g_sk;
        #pragma unroll
        for (int mf = 0; mf < 2; mf++) {
            int e0 = t * 64 + rowb + mf * 16 + g;
            #pragma unroll
            for (int hb = 0; hb < 2; hb++) {
                int n0 = 2 * hb, n1 = 2 * hb + 1;
                int c = colb + hb * 16 + 4 * tig;
                uint2 s0 = *(const uint2*)(skb + (size_t)e0 * 256 + c * 2);
                uint2 s1 = *(const uint2*)(skb + (size_t)(e0 + 8) * 256 + c * 2);
                float2 f0a = __half22float2(*(__half2*)&s0.x);
                float2 f0b = __half22float2(*(__half2*)&s0.y);
                float2 f1a = __half22float2(*(__half2*)&s1.x);
                float2 f1b = __half22float2(*(__half2*)&s1.y);
                float4 bb4 = *(const float4*)(bv + c);
                float4 v0, v1;
                v0.x = acc[mf][n0][0] + bb4.x + f0a.x;
                v0.y = acc[mf][n0][1] + bb4.y + f0a.y;
                v0.z = acc[mf][n1][0] + bb4.z + f0b.x;
                v0.w = acc[mf][n1][1] + bb4.w + f0b.y;
                v1.x = acc[mf][n0][2] + bb4.x + f1a.x;
                v1.y = acc[mf][n0][3] + bb4.y + f1a.y;
                v1.z = acc[mf][n1][2] + bb4.z + f1b.x;
                v1.w = acc[mf][n1][3] + bb4.w + f1b.y;
                *(float4*)(out + (size_t)e0 * OUT_CH + c) = v0;
                *(float4*)(out + (size_t)(e0 + 8) * OUT_CH + c) = v1;
            }
        }
        pre = pre_n;
        bar_grp(barid);   // Y buffer free for next Phase A
    }

    // signal completion so the other group never waits on us again
    if (gtid == 0) ((volatile int*)s_sync)[1 + grp] = 1;
}

extern "C" void kernel_launch(void* const* d_in, const int* in_sizes, int n_in,
                              void* d_out, int out_size) {
    (void)in_sizes; (void)n_in; (void)out_size;
    const int*   ei    = (const int*)d_in[0];
    const void*  mask  = d_in[1];
    const float* ea    = (const float*)d_in[2];
    const float* Win   = (const float*)d_in[3];
    const float* Wout  = (const float*)d_in[4];
    const float* Wskip = (const float*)d_in[5];
    const float* bskip = (const float*)d_in[6];
    const float* bias  = (const float*)d_in[7];
    float* out = (float*)d_out;

    int dev = 0;
    cudaGetDevice(&dev);
    int sms = 148;
    cudaDeviceGetAttribute(&sms, cudaDevAttrMultiProcessorCount, dev);

    void* hptr = nullptr;
    cudaGetSymbolAddress(&hptr, g_h);

    cudaFuncSetAttribute(stage1_kernel,
                         cudaFuncAttributeMaxDynamicSharedMemorySize, SMEM1);
    cudaFuncSetAttribute(stage2_kernel,
                         cudaFuncAttributeMaxDynamicSharedMemorySize, SMEM2);

    cudaMemsetAsync(hptr, 0, sizeof(float) * (size_t)NN * HID);
    stage1_kernel<<<sms * 2, 512, SMEM1>>>(ea, Win, Wskip, ei, mask);
    stage2_kernel<<<sms * 2, 512, SMEM2>>>(Wout, bskip, bias, ei, mask, out);
}